// round 1
// baseline (speedup 1.0000x reference)
#include <cuda_runtime.h>
#include <cuda_bf16.h>
#include <cstdint>

#define NUM_ENT 40000
#define ED      256      // embed dim
#define FD      768      // feat dim
#define BATCH   32
#define NE_OUT  (NUM_ENT + 1)    // 40001 scored entities
#define ET_LD   40128            // padded leading dim for Et (>= 40103, mult of 32)

// ---------------- device scratch (no runtime allocation allowed) ----------------
__device__ float          g_Et[ED * ET_LD];   // unity^T : [d][unity_row]  (~41 MB)
__device__ __nv_bfloat16  g_Bb[FD * ED];      // proj_W converted to bf16
__device__ float          g_qsum[ED * BATCH]; // query_sum, d-major [d][b]

// ---------------- small helpers ----------------
__device__ __forceinline__ unsigned long long addf32x2(unsigned long long a,
                                                       unsigned long long b) {
    unsigned long long r;
    asm("add.rn.f32x2 %0, %1, %2;" : "=l"(r) : "l"(a), "l"(b));
    return r;
}

__device__ __forceinline__ void ldsm4(uint32_t r[4], uint32_t addr) {
    asm volatile("ldmatrix.sync.aligned.m8n8.x4.shared.b16 {%0,%1,%2,%3}, [%4];"
                 : "=r"(r[0]), "=r"(r[1]), "=r"(r[2]), "=r"(r[3])
                 : "r"(addr));
}

__device__ __forceinline__ void mma16816(float c[4], const uint32_t a[4],
                                         uint32_t b0, uint32_t b1) {
    asm volatile(
        "mma.sync.aligned.m16n8k16.row.col.f32.bf16.bf16.f32 "
        "{%0,%1,%2,%3}, {%4,%5,%6,%7}, {%8,%9}, {%0,%1,%2,%3};"
        : "+f"(c[0]), "+f"(c[1]), "+f"(c[2]), "+f"(c[3])
        : "r"(a[0]), "r"(a[1]), "r"(a[2]), "r"(a[3]), "r"(b0), "r"(b1));
}

__device__ __forceinline__ uint32_t smaddr(const void* p) {
    return (uint32_t)__cvta_generic_to_shared(p);
}

// ---------------- kernel: convert proj_W fp32 -> bf16 ----------------
__global__ void convB_kernel(const float* __restrict__ W) {
    int i = blockIdx.x * 256 + threadIdx.x;
    if (i < FD * ED) g_Bb[i] = __float2bfloat16(W[i]);
}

// ---------------- kernel: fill unity rows 0 and 40001..40102 into Et ----------------
__global__ void fill_extra_kernel(const float* __restrict__ other) {
    int i = blockIdx.x * 256 + threadIdx.x;   // 103*256 elements
    if (i < 103 * ED) {
        int r = i / ED, d = i % ED;
        int col = (r == 0) ? 0 : (NUM_ENT + r);   // unity[40000+r] = other[r] (r>=1)
        g_Et[d * ET_LD + col] = other[i];
    }
}

// ---------------- GEMM: Et[n][1+m] = sum_k A[m,k]*W[n,k]  (bf16 HMMA) ----------------
// BM=128, BN=256(full), BK=32, 512 threads (16 warps: 4x4), warp tile 32x64.
#define BM       128
#define BK       32
#define ASTRIDE  40                    // padded smem row stride (bf16); conflict-free ldmatrix
#define A_ST     (BM * ASTRIDE)        // 5120 bf16 per stage
#define B_ST     (ED * ASTRIDE)        // 10240 bf16 per stage
#define GEMM_SMEM ((2 * A_ST + 2 * B_ST) * 2)  // 61440 bytes

__global__ void __launch_bounds__(512, 1) gemm_bf16_kernel(const float* __restrict__ A) {
    extern __shared__ __nv_bfloat16 sm[];
    __nv_bfloat16* sA = sm;               // two stages of A
    __nv_bfloat16* sB = sm + 2 * A_ST;    // two stages of B

    const int tid  = threadIdx.x;
    const int lane = tid & 31;
    const int warp = tid >> 5;
    const int wm   = warp >> 2;           // 0..3 -> 32 rows each
    const int wn   = warp & 3;            // 0..3 -> 64 cols each
    const int bm0  = blockIdx.x * BM;

    float acc[2][8][4];
#pragma unroll
    for (int i = 0; i < 2; i++)
#pragma unroll
        for (int j = 0; j < 8; j++)
#pragma unroll
            for (int k = 0; k < 4; k++) acc[i][j][k] = 0.f;

    // global-load slots
    const int arow0 = tid >> 3, acol = (tid & 7) * 4;   // A: 128 rows x 8 float4
    const int brow0 = tid >> 2, bcol = (tid & 3) * 8;   // B: 256 rows x 4 x(8 bf16)

    float4 va[2];
    uint4  vb[2];

    auto loadG = [&](int kc) {
#pragma unroll
        for (int i = 0; i < 2; i++) {
            int gr = bm0 + arow0 + i * 64;
            if (gr < NUM_ENT)
                va[i] = *(const float4*)(A + (size_t)gr * FD + kc + acol);
            else
                va[i] = make_float4(0.f, 0.f, 0.f, 0.f);
        }
#pragma unroll
        for (int i = 0; i < 2; i++) {
            int r = brow0 + i * 128;
            vb[i] = *(const uint4*)((const __nv_bfloat16*)g_Bb + r * FD + kc + bcol);
        }
    };
    auto stsStage = [&](int st) {
#pragma unroll
        for (int i = 0; i < 2; i++) {
            __nv_bfloat162 p0 = __floats2bfloat162_rn(va[i].x, va[i].y);
            __nv_bfloat162 p1 = __floats2bfloat162_rn(va[i].z, va[i].w);
            uint2 u;
            u.x = *(uint32_t*)&p0;
            u.y = *(uint32_t*)&p1;
            *(uint2*)&sA[st * A_ST + (arow0 + i * 64) * ASTRIDE + acol] = u;
        }
#pragma unroll
        for (int i = 0; i < 2; i++) {
            *(uint4*)&sB[st * B_ST + (brow0 + i * 128) * ASTRIDE + bcol] = vb[i];
        }
    };

    const int quad = lane >> 3, l8 = lane & 7;
    const int arow_l = (quad & 1) * 8 + l8;        // ldmatrix A row offset within 16
    const int acol_q = (quad >> 1) * 8;            // A col offset
    const int brow_l = (quad >> 1) * 8 + l8;       // ldmatrix B n-offset within 16
    const int bcol_q = (quad & 1) * 8;             // B k offset

    auto mmaStage = [&](int st) {
#pragma unroll
        for (int ks = 0; ks < 2; ks++) {
            const int k0 = ks * 16;
            uint32_t a[2][4], b[4][4];
#pragma unroll
            for (int mf = 0; mf < 2; mf++) {
                uint32_t ad = smaddr(&sA[st * A_ST +
                                         (wm * 32 + mf * 16 + arow_l) * ASTRIDE +
                                         k0 + acol_q]);
                ldsm4(a[mf], ad);
            }
#pragma unroll
            for (int nf2 = 0; nf2 < 4; nf2++) {
                uint32_t ad = smaddr(&sB[st * B_ST +
                                         (wn * 64 + nf2 * 16 + brow_l) * ASTRIDE +
                                         k0 + bcol_q]);
                ldsm4(b[nf2], ad);
            }
#pragma unroll
            for (int mf = 0; mf < 2; mf++)
#pragma unroll
                for (int nt = 0; nt < 8; nt++) {
                    mma16816(acc[mf][nt], a[mf],
                             b[nt >> 1][(nt & 1) * 2],
                             b[nt >> 1][(nt & 1) * 2 + 1]);
                }
        }
    };

    const int NC = FD / BK;   // 24
    loadG(0);
    stsStage(0);
    for (int c = 0; c < NC; c++) {
        __syncthreads();
        const int cst = c & 1, nst = (c + 1) & 1;
        if (c + 1 < NC) loadG((c + 1) * BK);
        mmaStage(cst);
        if (c + 1 < NC) stsStage(nst);
    }

    // epilogue: transposed store into g_Et[n][1+m]
    const int g = lane >> 2, tg = lane & 3;
#pragma unroll
    for (int mf = 0; mf < 2; mf++)
#pragma unroll
        for (int nt = 0; nt < 8; nt++) {
            int m = bm0 + wm * 32 + mf * 16 + g;
            int n = wn * 64 + nt * 8 + tg * 2;
            if (m < NUM_ENT) {
                g_Et[n * ET_LD + 1 + m]       = acc[mf][nt][0];
                g_Et[(n + 1) * ET_LD + 1 + m] = acc[mf][nt][1];
            }
            if (m + 8 < NUM_ENT) {
                g_Et[n * ET_LD + 9 + m]       = acc[mf][nt][2];
                g_Et[(n + 1) * ET_LD + 9 + m] = acc[mf][nt][3];
            }
        }
}

// ---------------- query_sum: gather 64 unity rows, L2-normalize, sum pairs ----------------
__global__ void __launch_bounds__(256) qsum_kernel(const void* __restrict__ ids_raw,
                                                   const int* __restrict__ mp_ptr) {
    __shared__ int s_ids[64];
    const int tid = threadIdx.x;
    if (tid == 0) {
        const int* p = (const int*)ids_raw;
        // detect int64 vs int32 storage: int64 little-endian -> odd int32 words are 0
        bool is64 = true;
        for (int i = 1; i < BATCH * 3; i += 2)
            if (p[i] != 0) { is64 = false; break; }
        int mp = 2;
        if (mp_ptr) {
            int im = *mp_ptr;
            if (im >= 0 && im < 3) mp = im;
            else {
                float f = __int_as_float(im);
                if (f >= 0.f && f < 3.f) mp = (int)f;
            }
        }
        for (int b = 0; b < BATCH; b++)
            for (int j = 0; j < 2; j++) {
                int col = (j < mp) ? j : j + 1;
                int idx = b * 3 + col;
                int id  = is64 ? (int)((const long long*)ids_raw)[idx] : p[idx];
                s_ids[b * 2 + j] = id;
            }
    }
    __syncthreads();

    const int warp = tid >> 5, lane = tid & 31;
    for (int b = warp * 4; b < warp * 4 + 4; b++) {
        float acc[8];
#pragma unroll
        for (int i = 0; i < 8; i++) acc[i] = 0.f;
        for (int j = 0; j < 2; j++) {
            const int id = s_ids[b * 2 + j];
            float v[8], ss = 0.f;
#pragma unroll
            for (int i = 0; i < 8; i++) {
                v[i] = g_Et[(lane + 32 * i) * ET_LD + id];
                ss += v[i] * v[i];
            }
#pragma unroll
            for (int o = 16; o > 0; o >>= 1)
                ss += __shfl_xor_sync(0xffffffffu, ss, o);
            float sc = 1.0f / fmaxf(sqrtf(ss), 1e-12f);
#pragma unroll
            for (int i = 0; i < 8; i++) acc[i] += v[i] * sc;
        }
#pragma unroll
        for (int i = 0; i < 8; i++)
            g_qsum[(lane + 32 * i) * BATCH + b] = acc[i];
    }
}

// ---------------- score: out[b][e] = -sum_d |q[b][d] - Et[d][e]| ----------------
__global__ void __launch_bounds__(256) score_kernel(float* __restrict__ out) {
    __shared__ float2 sq[ED][BATCH / 2];   // [d][b-pair], 32 KB
    const int tid = threadIdx.x;

    // cooperative q load (8192 floats = 2048 float4)
    const float4* qp = (const float4*)g_qsum;
    float4*       sp = (float4*)&sq[0][0];
#pragma unroll
    for (int i = 0; i < 8; i++) sp[tid + i * 256] = qp[tid + i * 256];
    __syncthreads();

    const int e = blockIdx.x * 256 + tid;
    if (e >= NE_OUT) return;

    unsigned long long acc[16];
#pragma unroll
    for (int bp = 0; bp < 16; bp++) acc[bp] = 0ULL;

    const float* ecol = g_Et + e;
#pragma unroll 2
    for (int d = 0; d < ED; d++) {
        float nv = -ecol[d * ET_LD];
        unsigned long long evn;
        asm("mov.b64 %0, {%1,%1};" : "=l"(evn) : "f"(nv));
        const unsigned long long* qrow = (const unsigned long long*)&sq[d][0];
#pragma unroll
        for (int bp = 0; bp < 16; bp++) {
            unsigned long long dif = addf32x2(qrow[bp], evn);
            dif &= 0x7FFFFFFF7FFFFFFFULL;      // |.| on both halves (ALU pipe)
            acc[bp] = addf32x2(acc[bp], dif);
        }
    }
#pragma unroll
    for (int bp = 0; bp < 16; bp++) {
        float lo = __int_as_float((int)(acc[bp] & 0xffffffffULL));
        float hi = __int_as_float((int)(acc[bp] >> 32));
        out[(size_t)(2 * bp) * NE_OUT + e]     = -lo;
        out[(size_t)(2 * bp + 1) * NE_OUT + e] = -hi;
    }
}

// ---------------- launcher ----------------
extern "C" void kernel_launch(void* const* d_in, const int* in_sizes, int n_in,
                              void* d_out, int out_size) {
    const float* ent   = (const float*)d_in[0];   // [40000,768] fp32
    const float* other = (const float*)d_in[1];   // [103,256]   fp32
    const float* W     = (const float*)d_in[2];   // [256,768]   fp32
    const void*  ids   = d_in[3];                 // [32,3] int32 or int64
    const int*   mp    = (n_in > 4) ? (const int*)d_in[4] : nullptr;

    cudaFuncSetAttribute(gemm_bf16_kernel,
                         cudaFuncAttributeMaxDynamicSharedMemorySize, GEMM_SMEM);

    convB_kernel<<<(FD * ED + 255) / 256, 256>>>(W);
    fill_extra_kernel<<<(103 * ED + 255) / 256, 256>>>(other);
    gemm_bf16_kernel<<<(NUM_ENT + BM - 1) / BM, 512, GEMM_SMEM>>>(ent);
    qsum_kernel<<<1, 256>>>(ids, mp);
    score_kernel<<<(NE_OUT + 255) / 256, 256>>>((float*)d_out);
}

// round 2
// speedup vs baseline: 1.2789x; 1.2789x over previous
#include <cuda_runtime.h>
#include <cuda_bf16.h>
#include <cstdint>

#define NUM_ENT 40000
#define ED      256      // embed dim
#define FD      768      // feat dim
#define BATCH   32
#define NE_OUT  (NUM_ENT + 1)    // 40001 scored entities
#define ET_LD   40128            // padded leading dim for Et

// ---------------- device scratch ----------------
__device__ float          g_Et[ED * ET_LD];   // unity^T : [d][unity_row]  (~41 MB)
__device__ __nv_bfloat16  g_Bb[FD * ED];      // proj_W converted to bf16
__device__ float          g_qsum[ED * BATCH]; // query_sum, d-major [d][b]

// ---------------- helpers ----------------
__device__ __forceinline__ unsigned long long addf32x2(unsigned long long a,
                                                       unsigned long long b) {
    unsigned long long r;
    asm("add.rn.f32x2 %0, %1, %2;" : "=l"(r) : "l"(a), "l"(b));
    return r;
}

__device__ __forceinline__ void ldsm4(uint32_t r[4], uint32_t addr) {
    asm volatile("ldmatrix.sync.aligned.m8n8.x4.shared.b16 {%0,%1,%2,%3}, [%4];"
                 : "=r"(r[0]), "=r"(r[1]), "=r"(r[2]), "=r"(r[3])
                 : "r"(addr));
}

__device__ __forceinline__ void mma16816(float c[4], const uint32_t a[4],
                                         uint32_t b0, uint32_t b1) {
    asm volatile(
        "mma.sync.aligned.m16n8k16.row.col.f32.bf16.bf16.f32 "
        "{%0,%1,%2,%3}, {%4,%5,%6,%7}, {%8,%9}, {%0,%1,%2,%3};"
        : "+f"(c[0]), "+f"(c[1]), "+f"(c[2]), "+f"(c[3])
        : "r"(a[0]), "r"(a[1]), "r"(a[2]), "r"(a[3]), "r"(b0), "r"(b1));
}

__device__ __forceinline__ uint32_t smaddr(const void* p) {
    return (uint32_t)__cvta_generic_to_shared(p);
}

// ---------------- prep: convert W to bf16 + fill unity edge rows ----------------
__global__ void prep_kernel(const float* __restrict__ W,
                            const float* __restrict__ other) {
    int i = blockIdx.x * 256 + threadIdx.x;
    if (i < FD * ED) g_Bb[i] = __float2bfloat16(W[i]);
    if (i < 103 * ED) {
        int r = i / ED, d = i % ED;
        int col = (r == 0) ? 0 : (NUM_ENT + r);
        g_Et[d * ET_LD + col] = other[i];
    }
}

// ---------------- GEMM: Et[n][1+m] = sum_k A[m,k]*W[n,k]  (bf16 HMMA) ----------------
#define BM       128
#define BK       32
#define ASTRIDE  40
#define A_ST     (BM * ASTRIDE)
#define B_ST     (ED * ASTRIDE)
#define GEMM_SMEM ((2 * A_ST + 2 * B_ST) * 2)

__global__ void __launch_bounds__(512, 1) gemm_bf16_kernel(const float* __restrict__ A) {
    extern __shared__ __nv_bfloat16 sm[];
    __nv_bfloat16* sA = sm;
    __nv_bfloat16* sB = sm + 2 * A_ST;

    const int tid  = threadIdx.x;
    const int lane = tid & 31;
    const int warp = tid >> 5;
    const int wm   = warp >> 2;
    const int wn   = warp & 3;
    const int bm0  = blockIdx.x * BM;

    float acc[2][8][4];
#pragma unroll
    for (int i = 0; i < 2; i++)
#pragma unroll
        for (int j = 0; j < 8; j++)
#pragma unroll
            for (int k = 0; k < 4; k++) acc[i][j][k] = 0.f;

    const int arow0 = tid >> 3, acol = (tid & 7) * 4;
    const int brow0 = tid >> 2, bcol = (tid & 3) * 8;

    float4 va[2];
    uint4  vb[2];

    auto loadG = [&](int kc) {
#pragma unroll
        for (int i = 0; i < 2; i++) {
            int gr = bm0 + arow0 + i * 64;
            if (gr < NUM_ENT)
                va[i] = *(const float4*)(A + (size_t)gr * FD + kc + acol);
            else
                va[i] = make_float4(0.f, 0.f, 0.f, 0.f);
        }
#pragma unroll
        for (int i = 0; i < 2; i++) {
            int r = brow0 + i * 128;
            vb[i] = *(const uint4*)((const __nv_bfloat16*)g_Bb + r * FD + kc + bcol);
        }
    };
    auto stsStage = [&](int st) {
#pragma unroll
        for (int i = 0; i < 2; i++) {
            __nv_bfloat162 p0 = __floats2bfloat162_rn(va[i].x, va[i].y);
            __nv_bfloat162 p1 = __floats2bfloat162_rn(va[i].z, va[i].w);
            uint2 u;
            u.x = *(uint32_t*)&p0;
            u.y = *(uint32_t*)&p1;
            *(uint2*)&sA[st * A_ST + (arow0 + i * 64) * ASTRIDE + acol] = u;
        }
#pragma unroll
        for (int i = 0; i < 2; i++) {
            *(uint4*)&sB[st * B_ST + (brow0 + i * 128) * ASTRIDE + bcol] = vb[i];
        }
    };

    const int quad = lane >> 3, l8 = lane & 7;
    const int arow_l = (quad & 1) * 8 + l8;
    const int acol_q = (quad >> 1) * 8;
    const int brow_l = (quad >> 1) * 8 + l8;
    const int bcol_q = (quad & 1) * 8;

    auto mmaStage = [&](int st) {
#pragma unroll
        for (int ks = 0; ks < 2; ks++) {
            const int k0 = ks * 16;
            uint32_t a[2][4], b[4][4];
#pragma unroll
            for (int mf = 0; mf < 2; mf++) {
                uint32_t ad = smaddr(&sA[st * A_ST +
                                         (wm * 32 + mf * 16 + arow_l) * ASTRIDE +
                                         k0 + acol_q]);
                ldsm4(a[mf], ad);
            }
#pragma unroll
            for (int nf2 = 0; nf2 < 4; nf2++) {
                uint32_t ad = smaddr(&sB[st * B_ST +
                                         (wn * 64 + nf2 * 16 + brow_l) * ASTRIDE +
                                         k0 + bcol_q]);
                ldsm4(b[nf2], ad);
            }
#pragma unroll
            for (int mf = 0; mf < 2; mf++)
#pragma unroll
                for (int nt = 0; nt < 8; nt++) {
                    mma16816(acc[mf][nt], a[mf],
                             b[nt >> 1][(nt & 1) * 2],
                             b[nt >> 1][(nt & 1) * 2 + 1]);
                }
        }
    };

    const int NC = FD / BK;
    loadG(0);
    stsStage(0);
    for (int c = 0; c < NC; c++) {
        __syncthreads();
        const int cst = c & 1, nst = (c + 1) & 1;
        if (c + 1 < NC) loadG((c + 1) * BK);
        mmaStage(cst);
        if (c + 1 < NC) stsStage(nst);
    }

    const int g = lane >> 2, tg = lane & 3;
#pragma unroll
    for (int mf = 0; mf < 2; mf++)
#pragma unroll
        for (int nt = 0; nt < 8; nt++) {
            int m = bm0 + wm * 32 + mf * 16 + g;
            int n = wn * 64 + nt * 8 + tg * 2;
            if (m < NUM_ENT) {
                g_Et[n * ET_LD + 1 + m]       = acc[mf][nt][0];
                g_Et[(n + 1) * ET_LD + 1 + m] = acc[mf][nt][1];
            }
            if (m + 8 < NUM_ENT) {
                g_Et[n * ET_LD + 9 + m]       = acc[mf][nt][2];
                g_Et[(n + 1) * ET_LD + 9 + m] = acc[mf][nt][3];
            }
        }
}

// ---------------- query_sum: one block per batch row ----------------
__global__ void __launch_bounds__(256) qsum_kernel(const void* __restrict__ ids_raw,
                                                   const int* __restrict__ mp_ptr) {
    __shared__ int   s_id[2];
    __shared__ float s_red[2][8];
    const int b = blockIdx.x, tid = threadIdx.x;

    if (tid == 0) {
        const int* p = (const int*)ids_raw;
        bool is64 = true;
        for (int i = 1; i < BATCH * 3; i += 2)
            if (p[i] != 0) { is64 = false; break; }
        int mp = 2;
        if (mp_ptr) {
            int im = *mp_ptr;
            if (im >= 0 && im < 3) mp = im;
            else {
                float f = __int_as_float(im);
                if (f >= 0.f && f < 3.f) mp = (int)f;
            }
        }
        for (int j = 0; j < 2; j++) {
            int col = (j < mp) ? j : j + 1;
            int idx = b * 3 + col;
            s_id[j] = is64 ? (int)((const long long*)ids_raw)[idx] : p[idx];
        }
    }
    __syncthreads();

    const int d = tid;
    float v0 = g_Et[d * ET_LD + s_id[0]];
    float v1 = g_Et[d * ET_LD + s_id[1]];
    float ss0 = v0 * v0, ss1 = v1 * v1;
#pragma unroll
    for (int o = 16; o > 0; o >>= 1) {
        ss0 += __shfl_xor_sync(0xffffffffu, ss0, o);
        ss1 += __shfl_xor_sync(0xffffffffu, ss1, o);
    }
    if ((tid & 31) == 0) {
        s_red[0][tid >> 5] = ss0;
        s_red[1][tid >> 5] = ss1;
    }
    __syncthreads();
    ss0 = 0.f; ss1 = 0.f;
#pragma unroll
    for (int w = 0; w < 8; w++) { ss0 += s_red[0][w]; ss1 += s_red[1][w]; }
    float r0 = 1.0f / fmaxf(sqrtf(ss0), 1e-12f);
    float r1 = 1.0f / fmaxf(sqrtf(ss1), 1e-12f);
    g_qsum[d * BATCH + b] = v0 * r0 + v1 * r1;
}

// ---------------- score: out[b][e] = -sum_d |q[b][d] - Et[d][e]| ----------------
__global__ void __launch_bounds__(256) score_kernel(float* __restrict__ out) {
    __shared__ float2 sq[ED][BATCH / 2];   // 32 KB
    const int tid = threadIdx.x;

    const float4* qp = (const float4*)g_qsum;
    float4*       sp = (float4*)&sq[0][0];
#pragma unroll
    for (int i = 0; i < 8; i++) sp[tid + i * 256] = qp[tid + i * 256];
    __syncthreads();

    const int e = blockIdx.x * 256 + tid;
    if (e >= NE_OUT) return;

    unsigned long long acc[16];
#pragma unroll
    for (int bp = 0; bp < 16; bp++) acc[bp] = 0ULL;

    const float* ecol = g_Et + e;

    float cur[4], nxt[4];
#pragma unroll
    for (int j = 0; j < 4; j++) cur[j] = ecol[j * ET_LD];

    auto body = [&](int d0, const float c[4]) {
#pragma unroll
        for (int j = 0; j < 4; j++) {
            float nv = -c[j];
            unsigned long long evn;
            asm("mov.b64 %0, {%1,%1};" : "=l"(evn) : "f"(nv));
            const unsigned long long* qrow =
                (const unsigned long long*)&sq[d0 + j][0];
#pragma unroll
            for (int bp = 0; bp < 16; bp++) {
                unsigned long long dif = addf32x2(qrow[bp], evn);
                dif &= 0x7FFFFFFF7FFFFFFFULL;
                acc[bp] = addf32x2(acc[bp], dif);
            }
        }
    };

    // software-pipelined: prefetch group d0+4 while computing group d0
    for (int d0 = 0; d0 < ED - 4; d0 += 4) {
#pragma unroll
        for (int j = 0; j < 4; j++) nxt[j] = ecol[(d0 + 4 + j) * ET_LD];
        body(d0, cur);
#pragma unroll
        for (int j = 0; j < 4; j++) cur[j] = nxt[j];
    }
    body(ED - 4, cur);   // epilogue group

#pragma unroll
    for (int bp = 0; bp < 16; bp++) {
        float lo = __int_as_float((int)(acc[bp] & 0xffffffffULL));
        float hi = __int_as_float((int)(acc[bp] >> 32));
        out[(size_t)(2 * bp) * NE_OUT + e]     = -lo;
        out[(size_t)(2 * bp + 1) * NE_OUT + e] = -hi;
    }
}

// ---------------- launcher ----------------
extern "C" void kernel_launch(void* const* d_in, const int* in_sizes, int n_in,
                              void* d_out, int out_size) {
    const float* ent   = (const float*)d_in[0];   // [40000,768] fp32
    const float* other = (const float*)d_in[1];   // [103,256]   fp32
    const float* W     = (const float*)d_in[2];   // [256,768]   fp32
    const void*  ids   = d_in[3];                 // [32,3]
    const int*   mp    = (n_in > 4) ? (const int*)d_in[4] : nullptr;

    cudaFuncSetAttribute(gemm_bf16_kernel,
                         cudaFuncAttributeMaxDynamicSharedMemorySize, GEMM_SMEM);

    prep_kernel<<<(FD * ED + 255) / 256, 256>>>(W, other);
    gemm_bf16_kernel<<<(NUM_ENT + BM - 1) / BM, 512, GEMM_SMEM>>>(ent);
    qsum_kernel<<<BATCH, 256>>>(ids, mp);
    score_kernel<<<(NE_OUT + 255) / 256, 256>>>((float*)d_out);
}

// round 3
// speedup vs baseline: 1.3286x; 1.0388x over previous
#include <cuda_runtime.h>
#include <cuda_bf16.h>
#include <cstdint>

#define NUM_ENT 40000
#define ED      256      // embed dim
#define FD      768      // feat dim
#define BATCH   32
#define NE_OUT  (NUM_ENT + 1)
#define ET_LD   40128    // padded leading dim

// Column layout of g_Et (all values stored NEGATED):
//   col c in [0,40000)   : -ent_proj[c]      (unity row c+1)
//   col 40000+r, r<103   : -other_emb[r]     (unity rows 0, 40001..40102)
// unity id -> col: id==0 -> 40000 ; 1<=id<=40000 -> id-1 ; id>40000 -> id
__device__ float          g_Et[ED * ET_LD];
__device__ __nv_bfloat16  g_Bb[FD * ED];
__device__ float          g_qsum[ED * BATCH];   // [d][b], TRUE (un-negated) qsum
__device__ int            g_qcol[BATCH * 2];    // gathered column ids

// ---------------- helpers ----------------
__device__ __forceinline__ unsigned long long addf32x2(unsigned long long a,
                                                       unsigned long long b) {
    unsigned long long r;
    asm("add.rn.f32x2 %0, %1, %2;" : "=l"(r) : "l"(a), "l"(b));
    return r;
}
__device__ __forceinline__ unsigned long long pack2(float x) {
    unsigned long long r;
    asm("mov.b64 %0, {%1,%1};" : "=l"(r) : "f"(x));
    return r;
}
__device__ __forceinline__ void ldsm4(uint32_t r[4], uint32_t addr) {
    asm volatile("ldmatrix.sync.aligned.m8n8.x4.shared.b16 {%0,%1,%2,%3}, [%4];"
                 : "=r"(r[0]), "=r"(r[1]), "=r"(r[2]), "=r"(r[3])
                 : "r"(addr));
}
__device__ __forceinline__ void mma16816(float c[4], const uint32_t a[4],
                                         uint32_t b0, uint32_t b1) {
    asm volatile(
        "mma.sync.aligned.m16n8k16.row.col.f32.bf16.bf16.f32 "
        "{%0,%1,%2,%3}, {%4,%5,%6,%7}, {%8,%9}, {%0,%1,%2,%3};"
        : "+f"(c[0]), "+f"(c[1]), "+f"(c[2]), "+f"(c[3])
        : "r"(a[0]), "r"(a[1]), "r"(a[2]), "r"(a[3]), "r"(b0), "r"(b1));
}
__device__ __forceinline__ uint32_t smaddr(const void* p) {
    return (uint32_t)__cvta_generic_to_shared(p);
}

// ---------------- prep kernels ----------------
__global__ void convB_kernel(const float* __restrict__ W) {
    int i = blockIdx.x * 256 + threadIdx.x;
    if (i < FD * ED) g_Bb[i] = __float2bfloat16(W[i]);
}
__global__ void fill_kernel(const float* __restrict__ other) {
    int i = blockIdx.x * 256 + threadIdx.x;
    if (i < 103 * ED) {
        int r = i / ED, d = i % ED;
        g_Et[d * ET_LD + NUM_ENT + r] = -other[i];
    }
}
__global__ void decode_ids_kernel(const void* __restrict__ ids_raw,
                                  const int* __restrict__ mp_ptr) {
    if (threadIdx.x != 0) return;
    const int* p = (const int*)ids_raw;
    bool is64 = true;
    for (int i = 1; i < BATCH * 3; i += 2)
        if (p[i] != 0) { is64 = false; break; }
    int mp = 2;
    if (mp_ptr) {
        int im = *mp_ptr;
        if (im >= 0 && im < 3) mp = im;
        else {
            float f = __int_as_float(im);
            if (f >= 0.f && f < 3.f) mp = (int)f;
        }
    }
    for (int b = 0; b < BATCH; b++)
        for (int j = 0; j < 2; j++) {
            int col3 = (j < mp) ? j : j + 1;
            int idx  = b * 3 + col3;
            int id   = is64 ? (int)((const long long*)ids_raw)[idx] : p[idx];
            int col  = (id == 0) ? NUM_ENT : (id <= NUM_ENT ? id - 1 : id);
            g_qcol[b * 2 + j] = col;
        }
}

// ---------------- GEMM: Et[n][bm0+m] = -sum_k A[m,k]*W[n,k] ----------------
#define BM       128
#define BK       32
#define ASTRIDE  40
#define A_ST     (BM * ASTRIDE)
#define B_ST     (ED * ASTRIDE)
#define GEMM_SMEM ((2 * A_ST + 2 * B_ST) * 2)   // 61440 B (>= 64*132*4 epilogue)

__global__ void __launch_bounds__(512, 1) gemm_bf16_kernel(const float* __restrict__ A) {
    extern __shared__ __nv_bfloat16 sm[];
    __nv_bfloat16* sA = sm;
    __nv_bfloat16* sB = sm + 2 * A_ST;

    const int tid  = threadIdx.x;
    const int lane = tid & 31;
    const int warp = tid >> 5;
    const int wm   = warp >> 2;
    const int wn   = warp & 3;
    const int bm0  = blockIdx.x * BM;

    float acc[2][8][4];
#pragma unroll
    for (int i = 0; i < 2; i++)
#pragma unroll
        for (int j = 0; j < 8; j++)
#pragma unroll
            for (int k = 0; k < 4; k++) acc[i][j][k] = 0.f;

    const int arow0 = tid >> 3, acol = (tid & 7) * 4;
    const int brow0 = tid >> 2, bcol = (tid & 3) * 8;

    float4 va[2];
    uint4  vb[2];

    auto loadG = [&](int kc) {
#pragma unroll
        for (int i = 0; i < 2; i++) {
            int gr = bm0 + arow0 + i * 64;
            if (gr < NUM_ENT)
                va[i] = *(const float4*)(A + (size_t)gr * FD + kc + acol);
            else
                va[i] = make_float4(0.f, 0.f, 0.f, 0.f);
        }
#pragma unroll
        for (int i = 0; i < 2; i++) {
            int r = brow0 + i * 128;
            vb[i] = *(const uint4*)((const __nv_bfloat16*)g_Bb + r * FD + kc + bcol);
        }
    };
    auto stsStage = [&](int st) {
#pragma unroll
        for (int i = 0; i < 2; i++) {
            __nv_bfloat162 p0 = __floats2bfloat162_rn(va[i].x, va[i].y);
            __nv_bfloat162 p1 = __floats2bfloat162_rn(va[i].z, va[i].w);
            uint2 u;
            u.x = *(uint32_t*)&p0;
            u.y = *(uint32_t*)&p1;
            *(uint2*)&sA[st * A_ST + (arow0 + i * 64) * ASTRIDE + acol] = u;
        }
#pragma unroll
        for (int i = 0; i < 2; i++) {
            *(uint4*)&sB[st * B_ST + (brow0 + i * 128) * ASTRIDE + bcol] = vb[i];
        }
    };

    const int quad = lane >> 3, l8 = lane & 7;
    const int arow_l = (quad & 1) * 8 + l8;
    const int acol_q = (quad >> 1) * 8;
    const int brow_l = (quad >> 1) * 8 + l8;
    const int bcol_q = (quad & 1) * 8;

    auto mmaStage = [&](int st) {
#pragma unroll
        for (int ks = 0; ks < 2; ks++) {
            const int k0 = ks * 16;
            uint32_t a[2][4], b[4][4];
#pragma unroll
            for (int mf = 0; mf < 2; mf++) {
                uint32_t ad = smaddr(&sA[st * A_ST +
                                         (wm * 32 + mf * 16 + arow_l) * ASTRIDE +
                                         k0 + acol_q]);
                ldsm4(a[mf], ad);
            }
#pragma unroll
            for (int nf2 = 0; nf2 < 4; nf2++) {
                uint32_t ad = smaddr(&sB[st * B_ST +
                                         (wn * 64 + nf2 * 16 + brow_l) * ASTRIDE +
                                         k0 + bcol_q]);
                ldsm4(b[nf2], ad);
            }
#pragma unroll
            for (int mf = 0; mf < 2; mf++)
#pragma unroll
                for (int nt = 0; nt < 8; nt++) {
                    mma16816(acc[mf][nt], a[mf],
                             b[nt >> 1][(nt & 1) * 2],
                             b[nt >> 1][(nt & 1) * 2 + 1]);
                }
        }
    };

    const int NC = FD / BK;
    loadG(0);
    stsStage(0);
    for (int c = 0; c < NC; c++) {
        __syncthreads();
        const int cst = c & 1, nst = (c + 1) & 1;
        if (c + 1 < NC) loadG((c + 1) * BK);
        mmaStage(cst);
        if (c + 1 < NC) stsStage(nst);
    }
    __syncthreads();

    // staged, coalesced epilogue: 4 chunks of 64 n-rows, stores NEGATED
    float* s_out = (float*)sm;                 // [64][132]
    const int g = lane >> 2, tg = lane & 3;
#pragma unroll
    for (int chunk = 0; chunk < 4; chunk++) {
        if (wn == chunk) {
#pragma unroll
            for (int mf = 0; mf < 2; mf++)
#pragma unroll
                for (int nt = 0; nt < 8; nt++) {
                    int srow = nt * 8 + tg * 2;
                    int scol = wm * 32 + mf * 16 + g;
                    s_out[srow * 132 + scol]           = -acc[mf][nt][0];
                    s_out[(srow + 1) * 132 + scol]     = -acc[mf][nt][1];
                    s_out[srow * 132 + scol + 8]       = -acc[mf][nt][2];
                    s_out[(srow + 1) * 132 + scol + 8] = -acc[mf][nt][3];
                }
        }
        __syncthreads();
#pragma unroll
        for (int i = 0; i < 4; i++) {
            int idx = tid + i * 512;           // 0..2047
            int n = idx >> 5, m4 = idx & 31;
            if (bm0 + m4 * 4 + 4 <= NUM_ENT) {
                float4 v = *(float4*)&s_out[n * 132 + m4 * 4];
                *(float4*)&g_Et[(size_t)(chunk * 64 + n) * ET_LD + bm0 + m4 * 4] = v;
            }
        }
        __syncthreads();
    }
}

// ---------------- query_sum: one block per batch row ----------------
__global__ void __launch_bounds__(256) qsum_kernel() {
    __shared__ float s_red[2][8];
    const int b = blockIdx.x, tid = threadIdx.x;
    const int c0 = g_qcol[b * 2], c1 = g_qcol[b * 2 + 1];

    const int d = tid;
    float v0 = g_Et[d * ET_LD + c0];   // negated unity values
    float v1 = g_Et[d * ET_LD + c1];
    float ss0 = v0 * v0, ss1 = v1 * v1;
#pragma unroll
    for (int o = 16; o > 0; o >>= 1) {
        ss0 += __shfl_xor_sync(0xffffffffu, ss0, o);
        ss1 += __shfl_xor_sync(0xffffffffu, ss1, o);
    }
    if ((tid & 31) == 0) { s_red[0][tid >> 5] = ss0; s_red[1][tid >> 5] = ss1; }
    __syncthreads();
    ss0 = 0.f; ss1 = 0.f;
#pragma unroll
    for (int w = 0; w < 8; w++) { ss0 += s_red[0][w]; ss1 += s_red[1][w]; }
    // stored values are negated -> flip sign of scale to recover TRUE qsum
    float r0 = -1.0f / fmaxf(sqrtf(ss0), 1e-12f);
    float r1 = -1.0f / fmaxf(sqrtf(ss1), 1e-12f);
    g_qsum[d * BATCH + b] = v0 * r0 + v1 * r1;
}

// ---------------- score ----------------
// grid (79, 4): block = 512 cols x 8 batches. thread: 2 adjacent cols, 8 batches.
// Et stores -e, so |q - e| = abs(add.f32x2(q, e_stored)).
__global__ void __launch_bounds__(256) score_kernel(float* __restrict__ out) {
    __shared__ unsigned long long sq[ED][4];   // 8 KB: [d][batch-pair within group]
    const int tid = threadIdx.x;
    const int by  = blockIdx.y;                // batch group: batches 8*by..8*by+7

    {
        float4* dst = (float4*)&sq[0][0];
#pragma unroll
        for (int i = 0; i < 2; i++) {
            int idx = tid + i * 256;           // 0..511
            int d = idx >> 1, h = idx & 1;
            dst[d * 2 + h] =
                *(const float4*)(g_qsum + d * BATCH + by * 8 + h * 4);
        }
    }
    __syncthreads();

    int c0 = (blockIdx.x * 256 + tid) * 2;
    const bool active = (c0 <= NUM_ENT);
    const int  cc = active ? c0 : 0;
    const float* ecol = g_Et + cc;

    unsigned long long acc[8];
#pragma unroll
    for (int i = 0; i < 8; i++) acc[i] = 0ULL;

    float2 cur[4], nxt[4];
#pragma unroll
    for (int j = 0; j < 4; j++) cur[j] = *(const float2*)(ecol + j * ET_LD);

    auto body = [&](int d0, const float2 c[4]) {
#pragma unroll
        for (int j = 0; j < 4; j++) {
            unsigned long long e0 = pack2(c[j].x);
            unsigned long long e1 = pack2(c[j].y);
            const unsigned long long* qr = sq[d0 + j];
#pragma unroll
            for (int bp = 0; bp < 4; bp++) {
                unsigned long long q = qr[bp];
                unsigned long long da = addf32x2(q, e0) & 0x7FFFFFFF7FFFFFFFULL;
                unsigned long long db = addf32x2(q, e1) & 0x7FFFFFFF7FFFFFFFULL;
                acc[bp]     = addf32x2(acc[bp], da);
                acc[4 + bp] = addf32x2(acc[4 + bp], db);
            }
        }
    };

    for (int d0 = 0; d0 < ED - 4; d0 += 4) {
#pragma unroll
        for (int j = 0; j < 4; j++)
            nxt[j] = *(const float2*)(ecol + (d0 + 4 + j) * ET_LD);
        body(d0, cur);
#pragma unroll
        for (int j = 0; j < 4; j++) cur[j] = nxt[j];
    }
    body(ED - 4, cur);

    if (active) {
#pragma unroll
        for (int j = 0; j < 2; j++) {
            int c = c0 + j;
            if (c <= NUM_ENT) {
                int e = (c == NUM_ENT) ? 0 : c + 1;
#pragma unroll
                for (int bp = 0; bp < 4; bp++) {
                    unsigned long long a = acc[j * 4 + bp];
                    float lo = __int_as_float((int)(a & 0xffffffffULL));
                    float hi = __int_as_float((int)(a >> 32));
                    int b = 8 * by + 2 * bp;
                    out[(size_t)b * NE_OUT + e]       = -lo;
                    out[(size_t)(b + 1) * NE_OUT + e] = -hi;
                }
            }
        }
    }
}

// ---------------- launcher ----------------
extern "C" void kernel_launch(void* const* d_in, const int* in_sizes, int n_in,
                              void* d_out, int out_size) {
    const float* ent   = (const float*)d_in[0];
    const float* other = (const float*)d_in[1];
    const float* W     = (const float*)d_in[2];
    const void*  ids   = d_in[3];
    const int*   mp    = (n_in > 4) ? (const int*)d_in[4] : nullptr;

    cudaFuncSetAttribute(gemm_bf16_kernel,
                         cudaFuncAttributeMaxDynamicSharedMemorySize, GEMM_SMEM);

    convB_kernel<<<(FD * ED + 255) / 256, 256>>>(W);
    fill_kernel<<<(103 * ED + 255) / 256, 256>>>(other);
    decode_ids_kernel<<<1, 32>>>(ids, mp);
    gemm_bf16_kernel<<<(NUM_ENT + BM - 1) / BM, 512, GEMM_SMEM>>>(ent);
    qsum_kernel<<<BATCH, 256>>>();
    dim3 sg((NUM_ENT / 2 + 255) / 256 + 1, 4);   // 79 x 4
    score_kernel<<<sg, 256>>>((float*)d_out);
}